// round 1
// baseline (speedup 1.0000x reference)
#include <cuda_runtime.h>
#include <cstdint>
#include <float.h>

#define B_ 128
#define H_ 14
#define W_ 14
#define C_ 512
#define HW_ (H_ * W_)
#define ITERS_ 10

// Scratch: final cluster assignment per (b, c), 1 byte each, word-aligned.
__device__ unsigned int g_assign_words[(B_ * C_) / 4];

// ---------------------------------------------------------------------------
// Kernel 1: per-(b,c) spatial argmax -> points, then K=2 k-means (11 steps)
// One block per batch, one thread per channel. Fully coalesced input reads.
// ---------------------------------------------------------------------------
__global__ __launch_bounds__(C_, 1) void argmax_kmeans_kernel(
    const float* __restrict__ in)
{
    const int b = blockIdx.x;
    const int c = threadIdx.x;

    __shared__ float spx[C_];
    __shared__ float spy[C_];
    __shared__ float sred[48];  // 16 warp partials x 3 values

    // ---- spatial argmax (first occurrence, row-major h*14+w scan) ----
    const float* base = in + (size_t)b * HW_ * C_ + c;
    float best = -FLT_MAX;
    int bestIdx = 0;
#pragma unroll 7
    for (int i = 0; i < HW_; i++) {
        float v = __ldg(base + (size_t)i * C_);
        if (v > best) { best = v; bestIdx = i; }
    }
    const float px = (float)(bestIdx % W_);  // arg1: W coordinate
    const float py = (float)(bestIdx / W_);  // arg0: H coordinate

    spx[c] = px;
    spy[c] = py;
    __syncthreads();

    // initial centroids = points of channels 0 and 1
    float c0x = spx[0], c0y = spy[0];
    float c1x = spx[1], c1y = spy[1];

    const int lane = c & 31;
    const int warp = c >> 5;

    // ---- totals Sx, Sy (exact integer sums in fp32) ----
    float ta = px, tb = py;
#pragma unroll
    for (int off = 16; off; off >>= 1) {
        ta += __shfl_down_sync(0xffffffffu, ta, off);
        tb += __shfl_down_sync(0xffffffffu, tb, off);
    }
    if (lane == 0) { sred[warp] = ta; sred[16 + warp] = tb; }
    __syncthreads();
    float Sx = 0.f, Sy = 0.f;
#pragma unroll
    for (int i = 0; i < 16; i++) { Sx += sred[i]; Sy += sred[16 + i]; }
    __syncthreads();

    int assign = 0;
    for (int it = 0; it <= ITERS_; it++) {
        const float dx0 = px - c0x, dy0 = py - c0y;
        const float dx1 = px - c1x, dy1 = py - c1y;
        const float d0 = dx0 * dx0 + dy0 * dy0;
        const float d1 = dx1 * dx1 + dy1 * dy1;
        assign = (d1 < d0) ? 1 : 0;  // argmin tie -> cluster 0

        // reduce sums over assign==1 members (exact integer arithmetic)
        float sx1 = assign ? px : 0.f;
        float sy1 = assign ? py : 0.f;
        float n1f = (float)assign;
#pragma unroll
        for (int off = 16; off; off >>= 1) {
            sx1 += __shfl_down_sync(0xffffffffu, sx1, off);
            sy1 += __shfl_down_sync(0xffffffffu, sy1, off);
            n1f += __shfl_down_sync(0xffffffffu, n1f, off);
        }
        if (lane == 0) {
            sred[warp] = sx1; sred[16 + warp] = sy1; sred[32 + warp] = n1f;
        }
        __syncthreads();
        float Tx1 = 0.f, Ty1 = 0.f, Tn1 = 0.f;
#pragma unroll
        for (int i = 0; i < 16; i++) {
            Tx1 += sred[i]; Ty1 += sred[16 + i]; Tn1 += sred[32 + i];
        }
        __syncthreads();

        const float Tx0 = Sx - Tx1, Ty0 = Sy - Ty1;
        const float Tn0 = (float)C_ - Tn1;
        const float inv1 = 1.0f / fmaxf(Tn1, 1.0f);
        const float inv0 = 1.0f / fmaxf(Tn0, 1.0f);
        // reference swaps: new cent[0] = mean of cluster-1 points, etc.
        c0x = Tx1 * inv1; c0y = Ty1 * inv1;
        c1x = Tx0 * inv0; c1y = Ty0 * inv0;
    }

    // byte store of the final assignment
    ((unsigned char*)g_assign_words)[b * C_ + c] = (unsigned char)assign;
}

// ---------------------------------------------------------------------------
// Kernel 2: streaming mask split. float4 per thread (4 consecutive channels).
// ---------------------------------------------------------------------------
__global__ __launch_bounds__(256) void mask_kernel(
    const float4* __restrict__ in, float4* __restrict__ out0,
    float4* __restrict__ out1)
{
    const int n4 = (B_ * HW_ * C_) / 4;
    const int i = blockIdx.x * blockDim.x + threadIdx.x;
    if (i >= n4) return;

    const int C4 = C_ / 4;
    const int c4 = i % C4;           // which channel-quad
    const int b = i / (C4 * HW_);    // batch

    const unsigned int am = g_assign_words[(b * C_) / 4 + c4];
    const float4 x = __ldg(in + i);

    float4 z0, z1;
    const bool m0 = (am & 0x000000ffu) != 0;
    const bool m1 = (am & 0x0000ff00u) != 0;
    const bool m2 = (am & 0x00ff0000u) != 0;
    const bool m3 = (am & 0xff000000u) != 0;
    z1.x = m0 ? x.x : 0.f;  z0.x = m0 ? 0.f : x.x;
    z1.y = m1 ? x.y : 0.f;  z0.y = m1 ? 0.f : x.y;
    z1.z = m2 ? x.z : 0.f;  z0.z = m2 ? 0.f : x.z;
    z1.w = m3 ? x.w : 0.f;  z0.w = m3 ? 0.f : x.w;

    out0[i] = z0;  // C0: kept where assign==0
    out1[i] = z1;  // C1: kept where assign==1
}

extern "C" void kernel_launch(void* const* d_in, const int* in_sizes, int n_in,
                              void* d_out, int out_size)
{
    const float* in = (const float*)d_in[0];
    float* out = (float*)d_out;
    const int n_elem = B_ * HW_ * C_;  // 12,845,056

    argmax_kmeans_kernel<<<B_, C_>>>(in);

    const int n4 = n_elem / 4;
    const int threads = 256;
    const int blocks = (n4 + threads - 1) / threads;
    mask_kernel<<<blocks, threads>>>((const float4*)in, (float4*)out,
                                     (float4*)(out + n_elem));
}

// round 2
// speedup vs baseline: 1.4606x; 1.4606x over previous
#include <cuda_runtime.h>
#include <cstdint>
#include <float.h>

#define B_ 128
#define H_ 14
#define W_ 14
#define C_ 512
#define HW_ (H_ * W_)
#define ITERS_ 10
#define NCHUNK 4
#define CHUNKLEN 49   // 196 / 4

// Scratch (device globals: no allocs allowed)
__device__ float g_pbest[B_ * NCHUNK * C_];          // 1 MB partial maxes
__device__ unsigned char g_pidx[B_ * NCHUNK * C_];   // 256 KB partial argmax (within chunk)
__device__ unsigned int g_assign_words[(B_ * C_) / 4];

// ---------------------------------------------------------------------------
// Kernel A: partial spatial argmax. grid (B, NCHUNK), 512 threads.
// Thread = one channel; scans CHUNKLEN spatial positions (coalesced, stride C).
// ---------------------------------------------------------------------------
__global__ __launch_bounds__(C_) void argmax_partial_kernel(
    const float* __restrict__ in)
{
    const int b = blockIdx.x;
    const int chunk = blockIdx.y;
    const int c = threadIdx.x;

    const float* base = in + ((size_t)b * HW_ + chunk * CHUNKLEN) * C_ + c;
    float best = -FLT_MAX;
    int bestIdx = 0;
#pragma unroll 7
    for (int i = 0; i < CHUNKLEN; i++) {
        float v = __ldg(base + (size_t)i * C_);
        if (v > best) { best = v; bestIdx = i; }
    }
    const int o = (b * NCHUNK + chunk) * C_ + c;
    g_pbest[o] = best;
    g_pidx[o] = (unsigned char)bestIdx;
}

// ---------------------------------------------------------------------------
// Kernel B: combine partials -> point per channel; histogram (196 bins);
// warp 0 runs 10 centroid updates with REDUX; all threads classify.
// grid = B, 512 threads.
// ---------------------------------------------------------------------------
__global__ __launch_bounds__(C_, 1) void kmeans_kernel()
{
    const int b = blockIdx.x;
    const int c = threadIdx.x;

    __shared__ int hist[HW_];
    __shared__ float sinit[4];   // init centroid coords (points 0 and 1)
    __shared__ float scent[4];   // final centroids

    // zero histogram
    if (c < HW_) hist[c] = 0;

    // combine the 4 chunk partials (in order -> first-occurrence semantics)
    float best = -FLT_MAX;
    int bestIdx = 0;
#pragma unroll
    for (int k = 0; k < NCHUNK; k++) {
        const int o = (b * NCHUNK + k) * C_ + c;
        const float v = g_pbest[o];
        if (v > best) { best = v; bestIdx = k * CHUNKLEN + (int)g_pidx[o]; }
    }
    const float px = (float)(bestIdx % W_);
    const float py = (float)(bestIdx / W_);

    if (c == 0) { sinit[0] = px; sinit[1] = py; }
    if (c == 1) { sinit[2] = px; sinit[3] = py; }
    __syncthreads();

    atomicAdd(&hist[bestIdx], 1);
    __syncthreads();

    if (c < 32) {
        // each lane owns 7 bins (lane*7 .. lane*7+6), bins >=196 are empty
        int cnt[7]; float bx[7], by[7];
        int sx = 0, sy = 0;
#pragma unroll
        for (int j = 0; j < 7; j++) {
            const int bin = c * 7 + j;
            const int n = (bin < HW_) ? hist[bin] : 0;
            cnt[j] = n;
            bx[j] = (float)(bin % W_);
            by[j] = (float)(bin / W_);
            sx += n * (bin % W_);
            sy += n * (bin / W_);
        }
        const int Sx = __reduce_add_sync(0xffffffffu, sx);
        const int Sy = __reduce_add_sync(0xffffffffu, sy);

        float c0x = sinit[0], c0y = sinit[1];
        float c1x = sinit[2], c1y = sinit[3];

        for (int it = 0; it < ITERS_; it++) {
            int s1x = 0, s1y = 0, n1 = 0;
#pragma unroll
            for (int j = 0; j < 7; j++) {
                const float dx0 = bx[j] - c0x, dy0 = by[j] - c0y;
                const float dx1 = bx[j] - c1x, dy1 = by[j] - c1y;
                const float d0 = dx0 * dx0 + dy0 * dy0;
                const float d1 = dx1 * dx1 + dy1 * dy1;
                const int m = (d1 < d0) ? cnt[j] : 0;
                n1 += m;
                s1x += m * (int)bx[j];
                s1y += m * (int)by[j];
            }
            const int T1x = __reduce_add_sync(0xffffffffu, s1x);
            const int T1y = __reduce_add_sync(0xffffffffu, s1y);
            const int T1n = __reduce_add_sync(0xffffffffu, n1);

            const float f1x = (float)T1x, f1y = (float)T1y, f1n = (float)T1n;
            const float f0x = (float)(Sx - T1x), f0y = (float)(Sy - T1y);
            const float f0n = (float)(C_ - T1n);
            const float inv1 = 1.0f / fmaxf(f1n, 1.0f);
            const float inv0 = 1.0f / fmaxf(f0n, 1.0f);
            // reference swaps clusters each update
            c0x = f1x * inv1; c0y = f1y * inv1;
            c1x = f0x * inv0; c1y = f0y * inv0;
        }
        if (c == 0) { scent[0] = c0x; scent[1] = c0y; scent[2] = c1x; scent[3] = c1y; }
    }
    __syncthreads();

    // final assignment (centroids after 10 updates = assigns[-1] in reference)
    const float dx0 = px - scent[0], dy0 = py - scent[1];
    const float dx1 = px - scent[2], dy1 = py - scent[3];
    const float d0 = dx0 * dx0 + dy0 * dy0;
    const float d1 = dx1 * dx1 + dy1 * dy1;
    const int assign = (d1 < d0) ? 1 : 0;
    ((unsigned char*)g_assign_words)[b * C_ + c] = (unsigned char)assign;
}

// ---------------------------------------------------------------------------
// Kernel C: streaming mask split. float4 per thread; __stcs keeps L2 for input.
// ---------------------------------------------------------------------------
__global__ __launch_bounds__(256) void mask_kernel(
    const float4* __restrict__ in, float4* __restrict__ out0,
    float4* __restrict__ out1)
{
    const int n4 = (B_ * HW_ * C_) / 4;
    const int i = blockIdx.x * blockDim.x + threadIdx.x;
    if (i >= n4) return;

    const int C4 = C_ / 4;
    const int c4 = i & (C4 - 1);
    const int b = i / (C4 * HW_);

    const unsigned int am = g_assign_words[b * C4 + c4];
    const float4 x = __ldg(in + i);

    float4 z0, z1;
    const bool m0 = (am & 0x000000ffu) != 0;
    const bool m1 = (am & 0x0000ff00u) != 0;
    const bool m2 = (am & 0x00ff0000u) != 0;
    const bool m3 = (am & 0xff000000u) != 0;
    z1.x = m0 ? x.x : 0.f;  z0.x = m0 ? 0.f : x.x;
    z1.y = m1 ? x.y : 0.f;  z0.y = m1 ? 0.f : x.y;
    z1.z = m2 ? x.z : 0.f;  z0.z = m2 ? 0.f : x.z;
    z1.w = m3 ? x.w : 0.f;  z0.w = m3 ? 0.f : x.w;

    __stcs(out0 + i, z0);   // streaming store: don't pollute L2
    __stcs(out1 + i, z1);
}

extern "C" void kernel_launch(void* const* d_in, const int* in_sizes, int n_in,
                              void* d_out, int out_size)
{
    const float* in = (const float*)d_in[0];
    float* out = (float*)d_out;
    const int n_elem = B_ * HW_ * C_;  // 12,845,056

    argmax_partial_kernel<<<dim3(B_, NCHUNK), C_>>>(in);
    kmeans_kernel<<<B_, C_>>>();

    const int n4 = n_elem / 4;
    mask_kernel<<<(n4 + 255) / 256, 256>>>((const float4*)in, (float4*)out,
                                           (float4*)(out + n_elem));
}